// round 8
// baseline (speedup 1.0000x reference)
#include <cuda_runtime.h>
#include <cstdint>

#define BATCH    512
#define BITD     64
#define NCLS     100
#define NTRAIN   100000
#define MARGIN_F 128.0f

#define BATCH_BLOCKS 128         // 4 rows per block
#define SCAN_BLOCKS  391         // ceil(100000/256)
#define UST_BLOCKS   512
#define FIX_BLOCKS   512
#define MEGA_BLOCKS  (SCAN_BLOCKS + UST_BLOCKS + FIX_BLOCKS)

// -------- device accumulators / scratch (no allocations allowed) --------
__device__ double   g_SUsq;           // sum_n |U'_n|^2 (ust + fix deltas)
__device__ double   g_corr;           // hinge corrections over mismatch pairs
// U column sums padded: one double per 128B line -> 64 distinct LTS slices,
// atomics to different columns never serialize on the same slice.
__device__ double   g_SUpad[BITD * 16];
__device__ float    g_usq[BATCH];     // per-row |u_b|^2
__device__ __align__(16) unsigned g_ypk[4 * BATCH];   // packed labels [word][row]
__device__ __align__(16) float g_supart[BATCH_BLOCKS * BITD]; // u col partials
__device__ float    g_uqpart[BATCH_BLOCKS];  // per-block sum |u|^2 partials
__device__ float    g_s2part[BATCH_BLOCKS];  // per-block s2 partials
__device__ unsigned g_done;           // mega-block completion counter

__device__ __forceinline__ float wred(float v) {
#pragma unroll
    for (int o = 16; o; o >>= 1) v += __shfl_xor_sync(0xffffffffu, v, o);
    return v;
}
__device__ __forceinline__ double wredd(double v) {
#pragma unroll
    for (int o = 16; o; o >>= 1) v += __shfl_xor_sync(0xffffffffu, v, o);
    return v;
}

// --------- rare path: exact pair term 0.5*(max(m-d,0) - d) --------------
// Serial FMA chain: identical FP-op order wherever compiled -> the
// add-then-subtract cancellation across scan/fix roles is bit-exact.
__device__ __noinline__ double pair_term(int b, const float* __restrict__ ur,
                                         const float* __restrict__ vr) {
    float dot = 0.f, vsq = 0.f;
#pragma unroll 16
    for (int k = 0; k < BITD; k++) {
        float a = ur[k], c = vr[k];
        dot = fmaf(a, c, dot);
        vsq = fmaf(c, c, vsq);
    }
    float d = g_usq[b] - 2.f * dot + vsq;
    d = fmaxf(d, 0.f);
    return 0.5 * ((double)fmaxf(MARGIN_F - d, 0.f) - (double)d);
}

// Warp-cooperative permuted pack: lane l<25 supplies classes 4l..4l+3.
// Class c -> word (c&3), bit (c>>2); consistent everywhere; set
// intersection is permutation-invariant.
__device__ __forceinline__ uint4 pack_ballots_v(float4 v) {
    uint4 r;
    r.x = __ballot_sync(0xffffffffu, v.x != 0.f);
    r.y = __ballot_sync(0xffffffffu, v.y != 0.f);
    r.z = __ballot_sync(0xffffffffu, v.z != 0.f);
    r.w = __ballot_sync(0xffffffffu, v.w != 0.f);
    return r;
}
__device__ __forceinline__ uint4 pack_ballots(const float* __restrict__ row,
                                              int lane) {
    float4 v = make_float4(0.f, 0.f, 0.f, 0.f);
    if (lane < 25) v = ((const float4*)row)[lane];
    return pack_ballots_v(v);
}

// ------------- batch stats + y pack: 128 blocks, 4 rows per block --------
__global__ void __launch_bounds__(256)
k_batch(const float* __restrict__ u, const float* __restrict__ y) {
    __shared__ float scol[BITD];
    __shared__ float sv[8];               // [0..4) usq, [4..8) s2 per warp
    int t    = threadIdx.x;
    int lane = t & 31, warp = t >> 5;
    int row  = blockIdx.x * 4 + warp;     // 0..511

    if (t < BITD) scol[t] = 0.f;
    if (blockIdx.x == 0) {                // zero global accumulators
        if (t < BITD) g_SUpad[t * 16] = 0.0;
        if (t == 0) { g_SUsq = 0.0; g_corr = 0.0; g_done = 0u; }
    }
    __syncthreads();

    // u stats: lane owns columns 2*lane, 2*lane+1 of its row
    float2 v = ((const float2*)(u + row * BITD))[lane];
    float usq = v.x * v.x + v.y * v.y;
    float s2  = ((v.x > 0.f) ? 0.f : ((v.x < 0.f) ? 2.f : 1.f))
              + ((v.y > 0.f) ? 0.f : ((v.y < 0.f) ? 2.f : 1.f));
    atomicAdd(&scol[2 * lane],     v.x);  // 4-way conflict max (4 warps)
    atomicAdd(&scol[2 * lane + 1], v.y);
    float usqr = wred(usq);
    float s2r  = wred(s2);
    if (lane == 0) { g_usq[row] = usqr; sv[warp] = usqr; sv[4 + warp] = s2r; }

    // warp packs its row's labels
    uint4 b = pack_ballots(y + (size_t)row * NCLS, lane);
    if (lane == 0) {
        g_ypk[row]             = b.x;
        g_ypk[BATCH + row]     = b.y;
        g_ypk[2 * BATCH + row] = b.z;
        g_ypk[3 * BATCH + row] = b.w;
    }
    __syncthreads();

    if (t < BITD) g_supart[blockIdx.x * BITD + t] = scol[t];
    if (t == 0) {
        g_uqpart[blockIdx.x] = sv[0] + sv[1] + sv[2] + sv[3];
        g_s2part[blockIdx.x] = sv[4] + sv[5] + sv[6] + sv[7];
    }
}

// ------------- mega kernel: scan + U-stats + fix + finalize tail ---------
__global__ void __launch_bounds__(256)
k_mega(const float* __restrict__ u, const int* __restrict__ ind,
       const float* __restrict__ U, const float* __restrict__ Y,
       float* __restrict__ out) {
    __shared__ __align__(16) unsigned sh[4 * BATCH];  // 8KB
    __shared__ int      sind[BATCH];
    __shared__ float    scol[BITD + 8];
    __shared__ unsigned yn4[4];
    __shared__ int      s_last;
    __shared__ int      s_flag;

    int t    = threadIdx.x;
    int lane = t & 31, warp = t >> 5;

    if (blockIdx.x < SCAN_BLOCKS) {
        // ================= scan role =====================================
#pragma unroll
        for (int i = 0; i < 2; i++)
            ((uint4*)sh)[t + i * 256] = ((const uint4*)g_ypk)[t + i * 256];

        int n     = blockIdx.x * 256 + t;
        int nbase = blockIdx.x * 256 + warp * 32;

        // warp-cooperative pack, 4 rows of loads in flight per step
        unsigned w0 = 0, w1 = 0, w2 = 0, w3 = 0;
#pragma unroll
        for (int r0 = 0; r0 < 32; r0 += 4) {
            float4 vv[4];
#pragma unroll
            for (int rr = 0; rr < 4; rr++) {
                int nr = nbase + r0 + rr;
                if (nr >= NTRAIN) nr = NTRAIN - 1;
                vv[rr] = make_float4(0.f, 0.f, 0.f, 0.f);
                if (lane < 25)
                    vv[rr] = ((const float4*)(Y + (size_t)nr * NCLS))[lane];
            }
#pragma unroll
            for (int rr = 0; rr < 4; rr++) {
                uint4 b = pack_ballots_v(vv[rr]);
                if (lane == r0 + rr) { w0 = b.x; w1 = b.y; w2 = b.z; w3 = b.w; }
            }
        }
        __syncthreads();

        if (n < NTRAIN) {
            const uint4* sh4 = (const uint4*)sh;      // word-0 table as uint4
            double corr = 0.0;
#pragma unroll 4
            for (int b0i = 0; b0i < BATCH; b0i += 8) {
                uint4 pa = sh4[b0i >> 2];
                uint4 pb = sh4[(b0i >> 2) + 1];
                unsigned mna = min(min(pa.x & w0, pa.y & w0),
                                   min(pa.z & w0, pa.w & w0));
                unsigned mnb = min(min(pb.x & w0, pb.y & w0),
                                   min(pb.z & w0, pb.w & w0));
                if (min(mna, mnb) == 0u) {
#pragma unroll 1
                    for (int j = 0; j < 8; j++) {
                        int b = b0i + j;
                        unsigned r = (sh[b] & w0) | (sh[BATCH + b] & w1) |
                                     (sh[2 * BATCH + b] & w2) |
                                     (sh[3 * BATCH + b] & w3);
                        if (r == 0u)
                            corr += pair_term(b, u + b * BITD,
                                              U + (size_t)n * BITD);
                    }
                }
            }
            if (corr != 0.0) atomicAdd(&g_corr, corr);
        }
    } else if (blockIdx.x < SCAN_BLOCKS + UST_BLOCKS) {
        // ================= U stats role ==================================
        const int nth = UST_BLOCKS * 256;                 // 131072
        int gid = (blockIdx.x - SCAN_BLOCKS) * 256 + t;
        const float4* U4 = (const float4*)U;
        const int total4 = NTRAIN * BITD / 4;             // 1.6M

        float c0 = 0.f, c1 = 0.f, c2 = 0.f, c3 = 0.f, sq = 0.f;
#pragma unroll 4
        for (int i = gid; i < total4; i += nth) {
            float4 v = U4[i];
            c0 += v.x; c1 += v.y; c2 += v.z; c3 += v.w;
            sq += v.x * v.x + v.y * v.y + v.z * v.z + v.w * v.w;
        }
        int cbase = (4 * gid) & (BITD - 1);
        c0 += __shfl_xor_sync(0xffffffffu, c0, 16);
        c1 += __shfl_xor_sync(0xffffffffu, c1, 16);
        c2 += __shfl_xor_sync(0xffffffffu, c2, 16);
        c3 += __shfl_xor_sync(0xffffffffu, c3, 16);
        sq = wred(sq);

        if (t < BITD + 8) scol[t] = 0.f;
        __syncthreads();
        if (lane < 16) {
            atomicAdd(&scol[cbase],     c0);
            atomicAdd(&scol[cbase + 1], c1);
            atomicAdd(&scol[cbase + 2], c2);
            atomicAdd(&scol[cbase + 3], c3);
        }
        if (lane == 0) scol[BITD + warp] = sq;
        __syncthreads();
        if (t < BITD) atomicAdd(&g_SUpad[t * 16], (double)scol[t]);
        if (t == 0) {
            float s = 0.f;
#pragma unroll
            for (int w = 0; w < 8; w++) s += scol[BITD + w];
            atomicAdd(&g_SUsq, (double)s);
        }
    } else {
        // ================= fix role: one block per batch row =============
        int i = blockIdx.x - SCAN_BLOCKS - UST_BLOCKS;    // 0..511

        sind[t]       = ind[t];
        sind[t + 256] = ind[t + 256];
#pragma unroll
        for (int j = 0; j < 2; j++)
            ((uint4*)sh)[t + j * 256] = ((const uint4*)g_ypk)[t + j * 256];
        if (t == 0) s_last = 1;
        __syncthreads();

        int n = sind[i];
        for (int j = i + 1 + t; j < BATCH; j += 256)
            if (sind[j] == n) s_last = 0;
        __syncthreads();

        if (s_last) {
            if (warp == 0) {
                uint4 b = pack_ballots(Y + (size_t)n * NCLS, lane);
                if (lane == 0) { yn4[0] = b.x; yn4[1] = b.y;
                                 yn4[2] = b.z; yn4[3] = b.w; }
            }
            __syncthreads();

            unsigned yn0 = yn4[0], yn1 = yn4[1], yn2 = yn4[2], yn3 = yn4[3];
            unsigned m0 = sh[i],             m1 = sh[BATCH + i];
            unsigned m2 = sh[2 * BATCH + i], m3 = sh[3 * BATCH + i];
            double corr = 0.0;
#pragma unroll
            for (int bb = 0; bb < 2; bb++) {
                int b = t + bb * 256;
                unsigned ro = (sh[b] & yn0) | (sh[BATCH + b] & yn1) |
                              (sh[2 * BATCH + b] & yn2) |
                              (sh[3 * BATCH + b] & yn3);
                if (ro == 0u)   // remove scan's old-data contribution
                    corr -= pair_term(b, u + b * BITD, U + (size_t)n * BITD);
                unsigned rn = (sh[b] & m0) | (sh[BATCH + b] & m1) |
                              (sh[2 * BATCH + b] & m2) |
                              (sh[3 * BATCH + b] & m3);
                if (rn == 0u)   // add updated-data contribution
                    corr += pair_term(b, u + b * BITD, u + i * BITD);
            }
            if (corr != 0.0) atomicAdd(&g_corr, corr);

            // SU / SUsq deltas for the overwritten row (padded atomics)
            float dsq = 0.f;
            if (t < BITD) {
                float a = u[i * BITD + t];
                float c = U[(size_t)n * BITD + t];
                atomicAdd(&g_SUpad[t * 16], (double)(a - c));
                dsq = a * a - c * c;
                dsq = wred(dsq);
                if (lane == 0) atomicAdd(&g_SUsq, (double)dsq);
            }
        }
    }

    // ================= finalize tail: last block to finish ===============
    __threadfence();
    __syncthreads();
    if (t == 0)
        s_flag = (atomicAdd(&g_done, 1u) == MEGA_BLOCKS - 1) ? 1 : 0;
    __syncthreads();
    if (!s_flag) return;
    __threadfence();

    __shared__ double sterm[BITD];
    __shared__ double sparts[8];          // [0..4) usq, [4..8) s2

    // su[k] from 128 batch partials, dotted with completed SU[k]
    if (t < BITD) {
        double s = 0.0;
#pragma unroll 8
        for (int i = 0; i < BATCH_BLOCKS; i++)
            s += (double)g_supart[i * BITD + t];
        sterm[t] = s * g_SUpad[t * 16];
    }
    // sum_usq / s2 from 128 partials in double (warps 0..3 cover them)
    if (t < BATCH_BLOCKS) {
        double q = wredd((double)g_uqpart[t]);
        double a = wredd((double)g_s2part[t]);
        if (lane == 0) { sparts[warp] = q; sparts[4 + warp] = a; }
    }
    __syncthreads();

    if (t == 0) {
        double dotsum = 0.0;
#pragma unroll
        for (int k = 0; k < BITD; k++) dotsum += sterm[k];
        double sum_usq = sparts[0] + sparts[1] + sparts[2] + sparts[3];
        double s2sum   = sparts[4] + sparts[5] + sparts[6] + sparts[7];
        double sum_dist = (double)NTRAIN * sum_usq
                        + (double)BATCH  * g_SUsq
                        - 2.0 * dotsum;
        double loss1 = (0.5 * sum_dist + g_corr)
                     / ((double)BATCH * (double)NTRAIN);
        double loss2 = 0.1 * s2sum / ((double)BATCH * (double)BITD);
        out[0] = (float)(loss1 + loss2);
    }
}

// ------------------------------------------------------------ launcher
extern "C" void kernel_launch(void* const* d_in, const int* in_sizes, int n_in,
                              void* d_out, int out_size) {
    const float* u   = (const float*)d_in[0];   // [512, 64]
    const float* y   = (const float*)d_in[1];   // [512, 100]
    const int*   ind = (const int*)  d_in[2];   // [512]
    const float* U   = (const float*)d_in[3];   // [100000, 64]
    const float* Y   = (const float*)d_in[4];   // [100000, 100]
    float* out = (float*)d_out;

    k_batch<<<BATCH_BLOCKS, 256>>>(u, y);
    k_mega<<<MEGA_BLOCKS, 256>>>(u, ind, U, Y, out);
}